// round 10
// baseline (speedup 1.0000x reference)
#include <cuda_runtime.h>
#include <cuda_bf16.h>
#include <math.h>
#include <stdint.h>

// ---------------------------------------------------------------------------
// GatedDeltaNet  B=2 S=2048 H=2048 HK=16 HV=32 DK=DV=128 G=2 K=4
// Round 10 (R9 resubmit after infra flake, renorm threshold 1e-6):
//  - GEMM: 128x256 tile, 512 threads, 1 CTA/SM (16 warps share 1 barrier,
//    2x MMAs per sync), k32 double-buffer, panel swizzle kept
//  - scan: scaled-state trick (S_true = c*S^), removes elementwise decay:
//    3 FMA-ops/elem instead of 4, renorm when c < 1e-6
// ---------------------------------------------------------------------------

#define Sc    2048
#define Hc    2048
#define HKc   16
#define HVc   32
#define CDc   8192
#define FQ    12288
#define Mtot  4096
#define EPSc  1e-6f

// ------------------------------ scratch ------------------------------------
__device__ float g_qkvz[(size_t)Mtot * FQ];
__device__ float g_ba[Mtot * 64];
__device__ float g_bapart[8 * Mtot * 64];
__device__ float g_conv[(size_t)Mtot * CDc];
__device__ float g_qn[Mtot * 2048];
__device__ float g_kn[Mtot * 2048];
__device__ float g_gg[Mtot * HVc];
__device__ float g_beta[Mtot * HVc];
__device__ float g_opre[(size_t)Mtot * 4096];

__device__ __nv_bfloat16 g_xhi[(size_t)Mtot * Hc];
__device__ __nv_bfloat16 g_xlo[(size_t)Mtot * Hc];
__device__ __nv_bfloat16 g_bqhi[(size_t)FQ * Hc];
__device__ __nv_bfloat16 g_bqlo[(size_t)FQ * Hc];
__device__ __nv_bfloat16 g_bohi[(size_t)Hc * 4096];
__device__ __nv_bfloat16 g_bolo[(size_t)Hc * 4096];
__device__ __nv_bfloat16 g_ohi[(size_t)Mtot * 4096];
__device__ __nv_bfloat16 g_olo[(size_t)Mtot * 4096];

// ------------------------------ helpers ------------------------------------
__device__ __forceinline__ uint32_t smem_u32(const void* p) {
    uint32_t a;
    asm("{ .reg .u64 t; cvta.to.shared.u64 t, %1; cvt.u32.u64 %0, t; }"
        : "=r"(a) : "l"(p));
    return a;
}
__device__ __forceinline__ void cp_async16(uint32_t saddr, const void* gaddr) {
    asm volatile("cp.async.cg.shared.global [%0], [%1], 16;"
                 :: "r"(saddr), "l"(gaddr) : "memory");
}
__device__ __forceinline__ void cp_async4(uint32_t saddr, const void* gaddr) {
    asm volatile("cp.async.ca.shared.global [%0], [%1], 4;"
                 :: "r"(saddr), "l"(gaddr) : "memory");
}
__device__ __forceinline__ void cp_commit() {
    asm volatile("cp.async.commit_group;" ::: "memory");
}
template <int N>
__device__ __forceinline__ void cp_wait() {
    asm volatile("cp.async.wait_group %0;" :: "n"(N) : "memory");
}
__device__ __forceinline__ void mma16816(float* c, const uint32_t* a, const uint32_t* b) {
    asm volatile(
        "mma.sync.aligned.m16n8k16.row.col.f32.bf16.bf16.f32 "
        "{%0,%1,%2,%3}, {%4,%5,%6,%7}, {%8,%9}, {%0,%1,%2,%3};"
        : "+f"(c[0]), "+f"(c[1]), "+f"(c[2]), "+f"(c[3])
        : "r"(a[0]), "r"(a[1]), "r"(a[2]), "r"(a[3]), "r"(b[0]), "r"(b[1]));
}
__device__ __forceinline__ void ldsm4(uint32_t* r, uint32_t addr) {
    asm volatile("ldmatrix.sync.aligned.m8n8.x4.shared.b16 {%0,%1,%2,%3}, [%4];"
                 : "=r"(r[0]), "=r"(r[1]), "=r"(r[2]), "=r"(r[3]) : "r"(addr));
}

// ---------------------------------------------------------------------------
// fused 3-plane split-bf16 GEMM: C = Ah*Bh^T + Ah*Bl^T + Al*Bh^T
// block tile 128(M) x 256(N), 512 threads = 16 warps (4M x 4N), warp 32x64,
// K chunk 32, double-buffered, 1 CTA/SM, panel-swizzled 1D grid.
// ---------------------------------------------------------------------------
#define RS 40
#define AL_OFF  (128 * RS)                 // 5120 halves
#define BH_OFF  (2 * 128 * RS)             // 10240
#define BL_OFF  (BH_OFF + 256 * RS)        // 20480
#define STAGE_H (2 * 128 * RS + 2 * 256 * RS)   // 30720 halves
#define GEMM_SMEM (2 * STAGE_H * 2)        // 122880 bytes
#define GXP 8

__global__ void __launch_bounds__(512, 1) mma_gemm_kernel(
    const __nv_bfloat16* __restrict__ Ah, const __nv_bfloat16* __restrict__ Al,
    const __nv_bfloat16* __restrict__ Bh, const __nv_bfloat16* __restrict__ Bl,
    float* __restrict__ C, int Kd, int N)
{
    extern __shared__ __align__(16) __nv_bfloat16 sm[];
    const int t = threadIdx.x, lane = t & 31, w = t >> 5;
    const int wm = (w & 3) * 32, wn = (w >> 2) * 64;
    const int grp = lane >> 2, q = lane & 3;

    const int panel_sz = GXP * (Mtot / 128);
    const int panel = blockIdx.x / panel_sz;
    const int rem   = blockIdx.x % panel_sz;
    const int bx = panel * GXP + (rem % GXP);
    const int by = rem / GXP;

    const int kiters = Kd >> 5;

    float acc[2][8][4];
#pragma unroll
    for (int mi = 0; mi < 2; mi++)
#pragma unroll
        for (int ni = 0; ni < 8; ni++)
#pragma unroll
            for (int j = 0; j < 4; j++) acc[mi][ni][j] = 0.f;

    uint32_t smb = smem_u32(sm);

    // per-thread load slots: A planes 1 chunk each, B planes 2 chunks each
    const int ar = t >> 2, as = t & 3;
    const int br0 = t >> 2, bs0 = t & 3;
    const int br1 = (t + 512) >> 2, bs1 = (t + 512) & 3;

    auto issue = [&](int stage, int kc) {
        size_t k0 = (size_t)kc << 5;
        uint32_t sb = smb + (uint32_t)(stage * STAGE_H) * 2;
        const __nv_bfloat16* Ab  = Ah + (size_t)(by * 128) * Kd + k0;
        const __nv_bfloat16* Alb = Al + (size_t)(by * 128) * Kd + k0;
        const __nv_bfloat16* Bb  = Bh + (size_t)(bx * 256) * Kd + k0;
        const __nv_bfloat16* Blb = Bl + (size_t)(bx * 256) * Kd + k0;
        uint32_t soA = (uint32_t)(ar * RS + as * 8) * 2;
        cp_async16(sb + soA,              Ab  + (size_t)ar * Kd + as * 8);
        cp_async16(sb + AL_OFF * 2 + soA, Alb + (size_t)ar * Kd + as * 8);
        uint32_t so0 = (uint32_t)(br0 * RS + bs0 * 8) * 2;
        uint32_t so1 = (uint32_t)(br1 * RS + bs1 * 8) * 2;
        cp_async16(sb + BH_OFF * 2 + so0, Bb  + (size_t)br0 * Kd + bs0 * 8);
        cp_async16(sb + BL_OFF * 2 + so0, Blb + (size_t)br0 * Kd + bs0 * 8);
        cp_async16(sb + BH_OFF * 2 + so1, Bb  + (size_t)br1 * Kd + bs1 * 8);
        cp_async16(sb + BL_OFF * 2 + so1, Blb + (size_t)br1 * Kd + bs1 * 8);
        cp_commit();
    };

    issue(0, 0);

    const int r8  = lane & 7;
    const int hm  = (lane >> 3) & 1;
    const int hk2 = (lane >> 4) & 1;

    for (int it = 0; it < kiters; it++) {
        int buf = it & 1;
        cp_wait<0>();
        __syncthreads();
        if (it + 1 < kiters) issue(buf ^ 1, it + 1);

        uint32_t sb   = smb + (uint32_t)(buf * STAGE_H) * 2;
        uint32_t sahb = sb;
        uint32_t salb = sb + AL_OFF * 2;
        uint32_t sbhb = sb + BH_OFF * 2;
        uint32_t sblb = sb + BL_OFF * 2;

#pragma unroll
        for (int ks = 0; ks < 2; ks++) {
            const int k16 = ks * 16;
            uint32_t ah[2][4], al[2][4];
            uint32_t aoff0 = (uint32_t)((wm + hm * 8 + r8) * RS + k16 + hk2 * 8) * 2;
            uint32_t aoff1 = aoff0 + 16 * RS * 2;
            ldsm4(ah[0], sahb + aoff0);
            ldsm4(ah[1], sahb + aoff1);
            ldsm4(al[0], salb + aoff0);
            ldsm4(al[1], salb + aoff1);
#pragma unroll
            for (int pi = 0; pi < 4; pi++) {
                uint32_t boff = (uint32_t)((wn + pi * 16 + hk2 * 8 + r8) * RS + k16 + hm * 8) * 2;
                uint32_t bh4[4], bl4[4];
                ldsm4(bh4, sbhb + boff);
                ldsm4(bl4, sblb + boff);
                int n0 = pi * 2, n1 = pi * 2 + 1;
                mma16816(acc[0][n0], ah[0], bh4 + 0);
                mma16816(acc[1][n0], ah[1], bh4 + 0);
                mma16816(acc[0][n1], ah[0], bh4 + 2);
                mma16816(acc[1][n1], ah[1], bh4 + 2);
                mma16816(acc[0][n0], ah[0], bl4 + 0);
                mma16816(acc[1][n0], ah[1], bl4 + 0);
                mma16816(acc[0][n1], ah[0], bl4 + 2);
                mma16816(acc[1][n1], ah[1], bl4 + 2);
                mma16816(acc[0][n0], al[0], bh4 + 0);
                mma16816(acc[1][n0], al[1], bh4 + 0);
                mma16816(acc[0][n1], al[0], bh4 + 2);
                mma16816(acc[1][n1], al[1], bh4 + 2);
            }
        }
    }

    __syncthreads();
#pragma unroll
    for (int mi = 0; mi < 2; mi++) {
        int row = by * 128 + wm + mi * 16 + grp;
#pragma unroll
        for (int ni = 0; ni < 8; ni++) {
            int col = bx * 256 + wn + ni * 8 + q * 2;
            float2 v0 = make_float2(acc[mi][ni][0], acc[mi][ni][1]);
            float2 v1 = make_float2(acc[mi][ni][2], acc[mi][ni][3]);
            *reinterpret_cast<float2*>(C + (size_t)row * N + col) = v0;
            *reinterpret_cast<float2*>(C + (size_t)(row + 8) * N + col) = v1;
        }
    }
}

// ---------------------------------------------------------------------------
__global__ void split_kernel(const float* __restrict__ src,
                             __nv_bfloat16* __restrict__ hi,
                             __nv_bfloat16* __restrict__ lo)
{
    size_t i = (size_t)blockIdx.x * 256 + threadIdx.x;
    float v = src[i];
    __nv_bfloat16 h = __float2bfloat16(v);
    hi[i] = h;
    lo[i] = __float2bfloat16(v - __bfloat162float(h));
}

__global__ void transpose_split_kernel(const float* __restrict__ W,
                                       __nv_bfloat16* __restrict__ Th,
                                       __nv_bfloat16* __restrict__ Tl,
                                       int K, int N)
{
    __shared__ float tile[32][33];
    int n0 = blockIdx.x * 32, k0 = blockIdx.y * 32;
    int tx = threadIdx.x, ty = threadIdx.y;
#pragma unroll
    for (int j = 0; j < 4; j++)
        tile[ty + j * 8][tx] = W[(size_t)(k0 + ty + j * 8) * N + n0 + tx];
    __syncthreads();
#pragma unroll
    for (int j = 0; j < 4; j++) {
        float v = tile[tx][ty + j * 8];
        __nv_bfloat16 h = __float2bfloat16(v);
        size_t o = (size_t)(n0 + ty + j * 8) * K + k0 + tx;
        Th[o] = h;
        Tl[o] = __float2bfloat16(v - __bfloat162float(h));
    }
}

// ---------------------------------------------------------------------------
__global__ void __launch_bounds__(256) ba_part_kernel(
    const float* __restrict__ x, const float* __restrict__ w_ba)
{
    int ks = blockIdx.x, by = blockIdx.y;
    __shared__ float As[8][128];
    __shared__ float Bs[8][64];
    int t = threadIdx.x, tx = t & 15, ty = t >> 4;
    float acc[8][4];
#pragma unroll
    for (int i = 0; i < 8; i++)
#pragma unroll
        for (int j = 0; j < 4; j++) acc[i][j] = 0.f;

    int arow = t >> 1, acol4 = (t & 1) * 4;
    int brow = t >> 5, bcol2 = (t & 31) * 2;
    const float* Aptr = x + (size_t)(by * 128 + arow) * Hc + ks * 256;

    for (int k0 = 0; k0 < 256; k0 += 8) {
        float4 a4 = *reinterpret_cast<const float4*>(Aptr + k0 + acol4);
        As[acol4 + 0][arow] = a4.x; As[acol4 + 1][arow] = a4.y;
        As[acol4 + 2][arow] = a4.z; As[acol4 + 3][arow] = a4.w;
        float2 b2 = *reinterpret_cast<const float2*>(
            w_ba + (size_t)(ks * 256 + k0 + brow) * 64 + bcol2);
        Bs[brow][bcol2] = b2.x; Bs[brow][bcol2 + 1] = b2.y;
        __syncthreads();
#pragma unroll
        for (int kk = 0; kk < 8; kk++) {
            float a[8], b[4];
#pragma unroll
            for (int i = 0; i < 8; i++) a[i] = As[kk][ty * 8 + i];
#pragma unroll
            for (int j = 0; j < 4; j++) b[j] = Bs[kk][tx * 4 + j];
#pragma unroll
            for (int i = 0; i < 8; i++)
#pragma unroll
                for (int j = 0; j < 4; j++)
                    acc[i][j] = fmaf(a[i], b[j], acc[i][j]);
        }
        __syncthreads();
    }
    float* dst = g_bapart + (size_t)ks * Mtot * 64;
#pragma unroll
    for (int i = 0; i < 8; i++) {
        int row = by * 128 + ty * 8 + i;
        float4 v = make_float4(acc[i][0], acc[i][1], acc[i][2], acc[i][3]);
        *reinterpret_cast<float4*>(dst + (size_t)row * 64 + tx * 4) = v;
    }
}

__global__ void ba_reduce_kernel()
{
    int i = blockIdx.x * 256 + threadIdx.x;
    float s = 0.f;
#pragma unroll
    for (int ks = 0; ks < 8; ks++) s += g_bapart[(size_t)ks * Mtot * 64 + i];
    g_ba[i] = s;
}

// ---------------------------------------------------------------------------
__global__ void conv_qknorm_kernel(const float* __restrict__ conv_w,
                                   const float* __restrict__ conv_b)
{
    int tid = threadIdx.x;
    int c = blockIdx.x * 256 + tid;
    int m = blockIdx.y;
    int s = m & (Sc - 1);
    int col;
    if (c < 2048)      col = (c >> 7) * 768 + (c & 127);
    else if (c < 4096) { int c2 = c - 2048; col = (c2 >> 7) * 768 + 128 + (c2 & 127); }
    else               { int c3 = c - 4096; col = (c3 >> 8) * 768 + 256 + (c3 & 255); }
    float acc = conv_b[c];
    const float* w = conv_w + c * 4;
#pragma unroll
    for (int j = 0; j < 4; j++) {
        int sp = s - 3 + j;
        if (sp >= 0)
            acc = fmaf(g_qkvz[(size_t)(m - 3 + j) * FQ + col], w[j], acc);
    }
    float val = acc / (1.f + expf(-acc));

    if (c < 4096) {
        float ss = val * val;
#pragma unroll
        for (int o = 16; o > 0; o >>= 1) ss += __shfl_xor_sync(0xffffffffu, ss, o);
        __shared__ float rb[8];
        if ((tid & 31) == 0) rb[tid >> 5] = ss;
        __syncthreads();
        int hw = (tid >> 7) * 4;
        float sum = rb[hw] + rb[hw + 1] + rb[hw + 2] + rb[hw + 3];
        if (c < 2048) {
            float rq = rsqrtf(sum + EPSc) * 0.08838834764831845f;
            g_qn[m * 2048 + c] = val * rq;
        } else {
            float rk = rsqrtf(sum + EPSc);
            g_kn[m * 2048 + (c - 2048)] = val * rk;
        }
    } else {
        g_conv[(size_t)m * CDc + c] = val;
    }
}

__global__ void gbeta_kernel(const float* __restrict__ a_log,
                             const float* __restrict__ dt_bias)
{
    int idx = blockIdx.x * 256 + threadIdx.x;
    int m = idx >> 5, hv = idx & 31;
    int hk = hv >> 1, gi = hv & 1;
    float bval = g_ba[m * 64 + hk * 4 + gi];
    float aval = g_ba[m * 64 + hk * 4 + 2 + gi];
    float x = aval + dt_bias[hv];
    float sp = (x > 20.f) ? x : log1pf(expf(x));
    g_gg[idx]   = -expf(a_log[hv]) * sp;
    g_beta[idx] = 1.f / (1.f + expf(-bval));
}

// ---------------------------------------------------------------------------
// gated delta scan with scaled state: S_true = c * S^, c *= exp(g) per step.
// loop1: P = k.S^ (fma only); delta = (v - c*P)*beta; dc = delta/c;
// loop2: S^ += k*dc; o = c*(q.S^). Renorm S^ *= c when c < 1e-6.
// depth-2 prefetch, 128 blocks = (b,hv,vhalf), 256 threads.
// ---------------------------------------------------------------------------
__global__ void __launch_bounds__(256) scan_kernel()
{
    int bid = blockIdx.x;
    int bb = bid >> 6;
    int r = bid & 63;
    int hv = r >> 1, half = r & 1, hk = hv >> 1;
    int t = threadIdx.x;
    int vl = t & 63, qt = t >> 6, dbase = qt * 32;

    float S[32];
#pragma unroll
    for (int i = 0; i < 32; i++) S[i] = 0.f;
    float c = 1.f;

    __shared__ __align__(16) float kq[3][256];
    __shared__ __align__(16) float vsb[3][64];
    __shared__ float gbb[3][2];
    __shared__ float red[4][64], ored[4][64];

    const uint32_t skq = smem_u32(kq);
    const uint32_t svs = smem_u32(vsb);
    const uint32_t sgb = smem_u32(gbb);

    const float* kbase = g_kn + hk * 128;
    const float* qbase = g_qn + hk * 128;
    const float* vbase = g_conv + 4096 + hv * 128 + half * 64;
    const float* gbase = g_gg + hv;
    const float* bbase = g_beta + hv;

    auto prefetch = [&](int buf, int s) {
        int m = bb * Sc + s;
        if (t < 32)
            cp_async16(skq + buf * 1024 + t * 16, kbase + (size_t)m * 2048 + t * 4);
        else if (t < 64)
            cp_async16(skq + buf * 1024 + 512 + (t - 32) * 16,
                       qbase + (size_t)m * 2048 + (t - 32) * 4);
        else if (t < 80)
            cp_async16(svs + buf * 256 + (t - 64) * 16,
                       vbase + (size_t)m * CDc + (t - 64) * 4);
        else if (t == 80)
            cp_async4(sgb + buf * 8, gbase + m * 32);
        else if (t == 81)
            cp_async4(sgb + buf * 8 + 4, bbase + m * 32);
    };

    prefetch(0, 0); cp_commit();
    prefetch(1, 1); cp_commit();

    size_t obase = (size_t)bb * Sc * 4096 + hv * 128 + half * 64;

    for (int s = 0; s < Sc; s++) {
        int buf = s % 3;
        cp_wait<1>();
        __syncthreads();                      // bar1
        if (s + 2 < Sc) { prefetch((s + 2) % 3, s + 2); cp_commit(); }

        if (s > 0 && t < 64)
            g_opre[obase + (size_t)(s - 1) * 4096 + t] =
                ored[0][t] + ored[1][t] + ored[2][t] + ored[3][t];

        float eg   = expf(gbb[buf][0]);
        float beta = gbb[buf][1];
        const float* ks = kq[buf];
        const float* qs = kq[buf] + 128;
        const float* vs = vsb[buf];
        c *= eg;

        float p0 = 0.f, p1 = 0.f, p2 = 0.f, p3 = 0.f;
#pragma unroll
        for (int d = 0; d < 32; d += 4) {
            p0 = fmaf(ks[dbase + d],     S[d],     p0);
            p1 = fmaf(ks[dbase + d + 1], S[d + 1], p1);
            p2 = fmaf(ks[dbase + d + 2], S[d + 2], p2);
            p3 = fmaf(ks[dbase + d + 3], S[d + 3], p3);
        }
        red[qt][vl] = (p0 + p1) + (p2 + p3);
        __syncthreads();                      // bar2

        float P = red[0][vl] + red[1][vl] + red[2][vl] + red[3][vl];
        float delta = (vs[vl] - c * P) * beta;
        float dc = __fdividef(delta, c);
        float o0 = 0.f, o1 = 0.f, o2 = 0.f, o3 = 0.f;
#pragma unroll
        for (int d = 0; d < 32; d += 4) {
            S[d]     = fmaf(ks[dbase + d],     dc, S[d]);
            S[d + 1] = fmaf(ks[dbase + d + 1], dc, S[d + 1]);
            S[d + 2] = fmaf(ks[dbase + d + 2], dc, S[d + 2]);
            S[d + 3] = fmaf(ks[dbase + d + 3], dc, S[d + 3]);
            o0 = fmaf(qs[dbase + d],     S[d],     o0);
            o1 = fmaf(qs[dbase + d + 1], S[d + 1], o1);
            o2 = fmaf(qs[dbase + d + 2], S[d + 2], o2);
            o3 = fmaf(qs[dbase + d + 3], S[d + 3], o3);
        }
        ored[qt][vl] = ((o0 + o1) + (o2 + o3)) * c;

        if (c < 1e-6f) {                      // uniform across block
#pragma unroll
            for (int d = 0; d < 32; d++) S[d] *= c;
            c = 1.f;
        }
    }
    __syncthreads();
    if (t < 64)
        g_opre[obase + (size_t)(Sc - 1) * 4096 + t] =
            ored[0][t] + ored[1][t] + ored[2][t] + ored[3][t];
}

// ---------------------------------------------------------------------------
__global__ void gate_norm_kernel(const float* __restrict__ norm_w)
{
    int m = blockIdx.x, hv = blockIdx.y, d = threadIdx.x;
    int hk = hv >> 1, gi = hv & 1;
    float z = g_qkvz[(size_t)m * FQ + hk * 768 + 512 + gi * 128 + d];
    float o = g_opre[(size_t)m * 4096 + hv * 128 + d] * (z / (1.f + expf(-z)));
    float ss = o * o;
#pragma unroll
    for (int off = 16; off > 0; off >>= 1) ss += __shfl_xor_sync(0xffffffffu, ss, off);
    __shared__ float rb[4];
    if ((d & 31) == 0) rb[d >> 5] = ss;
    __syncthreads();
    float sum = rb[0] + rb[1] + rb[2] + rb[3];
    float rs = rsqrtf(sum * (1.f / 128.f) + EPSc);
    float v = o * rs * norm_w[d];
    __nv_bfloat16 h = __float2bfloat16(v);
    size_t idx = (size_t)m * 4096 + hv * 128 + d;
    g_ohi[idx] = h;
    g_olo[idx] = __float2bfloat16(v - __bfloat162float(h));
}

// ---------------------------------------------------------------------------
extern "C" void kernel_launch(void* const* d_in, const int* in_sizes, int n_in,
                              void* d_out, int out_size)
{
    const float* x       = (const float*)d_in[0];
    const float* w_qkvz  = (const float*)d_in[1];
    const float* w_ba    = (const float*)d_in[2];
    const float* a_log   = (const float*)d_in[3];
    const float* dt_bias = (const float*)d_in[4];
    const float* conv_w  = (const float*)d_in[5];
    const float* conv_b  = (const float*)d_in[6];
    const float* norm_w  = (const float*)d_in[7];
    const float* w_o     = (const float*)d_in[8];
    float* out = (float*)d_out;

    float *p_qkvz;
    __nv_bfloat16 *p_xhi, *p_xlo, *p_bqhi, *p_bqlo, *p_bohi, *p_bolo, *p_ohi, *p_olo;
    cudaGetSymbolAddress((void**)&p_qkvz, g_qkvz);
    cudaGetSymbolAddress((void**)&p_xhi,  g_xhi);
    cudaGetSymbolAddress((void**)&p_xlo,  g_xlo);
    cudaGetSymbolAddress((void**)&p_bqhi, g_bqhi);
    cudaGetSymbolAddress((void**)&p_bqlo, g_bqlo);
    cudaGetSymbolAddress((void**)&p_bohi, g_bohi);
    cudaGetSymbolAddress((void**)&p_bolo, g_bolo);
    cudaGetSymbolAddress((void**)&p_ohi,  g_ohi);
    cudaGetSymbolAddress((void**)&p_olo,  g_olo);

    cudaFuncSetAttribute(mma_gemm_kernel,
                         cudaFuncAttributeMaxDynamicSharedMemorySize, GEMM_SMEM);

    split_kernel<<<(Mtot * Hc) / 256, 256>>>(x, p_xhi, p_xlo);
    transpose_split_kernel<<<dim3(FQ / 32, Hc / 32), dim3(32, 8)>>>(w_qkvz, p_bqhi, p_bqlo, Hc, FQ);
    transpose_split_kernel<<<dim3(Hc / 32, 4096 / 32), dim3(32, 8)>>>(w_o, p_bohi, p_bolo, 4096, Hc);

    // K1: qkvz = x @ w_qkvz  (128x256 tiles, 1D swizzled grid)
    mma_gemm_kernel<<<(FQ / 256) * (Mtot / 128), 512, GEMM_SMEM>>>(
        p_xhi, p_xlo, p_bqhi, p_bqlo, p_qkvz, Hc, FQ);
    // K2: ba = x @ w_ba (split-K x8 + reduce)
    ba_part_kernel<<<dim3(8, Mtot / 128), 256>>>(x, w_ba);
    ba_reduce_kernel<<<(Mtot * 64) / 256, 256>>>();
    // K3+K4: conv + silu + q/k l2norm
    conv_qknorm_kernel<<<dim3(CDc / 256, Mtot), 256>>>(conv_w, conv_b);
    // K5: gates
    gbeta_kernel<<<(Mtot * HVc) / 256, 256>>>(a_log, dt_bias);
    // K6: recurrent scan (scaled-state)
    scan_kernel<<<128, 256>>>();
    // K7: gate + rmsnorm + bf16 split
    gate_norm_kernel<<<dim3(Mtot, HVc), 128>>>(norm_w);
    // K8: out = o @ w_o
    mma_gemm_kernel<<<(Hc / 256) * (Mtot / 128), 512, GEMM_SMEM>>>(
        p_ohi, p_olo, p_bohi, p_bolo, out, 4096, Hc);
}

// round 12
// speedup vs baseline: 1.0082x; 1.0082x over previous
#include <cuda_runtime.h>
#include <cuda_bf16.h>
#include <math.h>
#include <stdint.h>

// ---------------------------------------------------------------------------
// GatedDeltaNet  B=2 S=2048 H=2048 HK=16 HV=32 DK=DV=128 G=2 K=4
// Round 12 (R11 resubmit after second infra flake; source unchanged):
//  - GEMM: R8 config (128x128 tile, 256 thr, 2 CTA/SM, k32 dbuf, 1 sync/iter,
//    spacing-4 MMA order, panel swizzle) -- best measured: tensor 67.3%
//  - scan: R10 scaled-state (3 FMA-ops/elem, renorm @1e-6, depth-2 prefetch)
//  - split-K ba, fused conv+qknorm, gate_norm->bf16 direct
// ---------------------------------------------------------------------------

#define Sc    2048
#define Hc    2048
#define HKc   16
#define HVc   32
#define CDc   8192
#define FQ    12288
#define Mtot  4096
#define EPSc  1e-6f

// ------------------------------ scratch ------------------------------------
__device__ float g_qkvz[(size_t)Mtot * FQ];
__device__ float g_ba[Mtot * 64];
__device__ float g_bapart[8 * Mtot * 64];
__device__ float g_conv[(size_t)Mtot * CDc];
__device__ float g_qn[Mtot * 2048];
__device__ float g_kn[Mtot * 2048];
__device__ float g_gg[Mtot * HVc];
__device__ float g_beta[Mtot * HVc];
__device__ float g_opre[(size_t)Mtot * 4096];

__device__ __nv_bfloat16 g_xhi[(size_t)Mtot * Hc];
__device__ __nv_bfloat16 g_xlo[(size_t)Mtot * Hc];
__device__ __nv_bfloat16 g_bqhi[(size_t)FQ * Hc];
__device__ __nv_bfloat16 g_bqlo[(size_t)FQ * Hc];
__device__ __nv_bfloat16 g_bohi[(size_t)Hc * 4096];
__device__ __nv_bfloat16 g_bolo[(size_t)Hc * 4096];
__device__ __nv_bfloat16 g_ohi[(size_t)Mtot * 4096];
__device__ __nv_bfloat16 g_olo[(size_t)Mtot * 4096];

// ------------------------------ helpers ------------------------------------
__device__ __forceinline__ uint32_t smem_u32(const void* p) {
    uint32_t a;
    asm("{ .reg .u64 t; cvta.to.shared.u64 t, %1; cvt.u32.u64 %0, t; }"
        : "=r"(a) : "l"(p));
    return a;
}
__device__ __forceinline__ void cp_async16(uint32_t saddr, const void* gaddr) {
    asm volatile("cp.async.cg.shared.global [%0], [%1], 16;"
                 :: "r"(saddr), "l"(gaddr) : "memory");
}
__device__ __forceinline__ void cp_async4(uint32_t saddr, const void* gaddr) {
    asm volatile("cp.async.ca.shared.global [%0], [%1], 4;"
                 :: "r"(saddr), "l"(gaddr) : "memory");
}
__device__ __forceinline__ void cp_commit() {
    asm volatile("cp.async.commit_group;" ::: "memory");
}
template <int N>
__device__ __forceinline__ void cp_wait() {
    asm volatile("cp.async.wait_group %0;" :: "n"(N) : "memory");
}
__device__ __forceinline__ void mma16816(float* c, const uint32_t* a, const uint32_t* b) {
    asm volatile(
        "mma.sync.aligned.m16n8k16.row.col.f32.bf16.bf16.f32 "
        "{%0,%1,%2,%3}, {%4,%5,%6,%7}, {%8,%9}, {%0,%1,%2,%3};"
        : "+f"(c[0]), "+f"(c[1]), "+f"(c[2]), "+f"(c[3])
        : "r"(a[0]), "r"(a[1]), "r"(a[2]), "r"(a[3]), "r"(b[0]), "r"(b[1]));
}
__device__ __forceinline__ void ldsm4(uint32_t* r, uint32_t addr) {
    asm volatile("ldmatrix.sync.aligned.m8n8.x4.shared.b16 {%0,%1,%2,%3}, [%4];"
                 : "=r"(r[0]), "=r"(r[1]), "=r"(r[2]), "=r"(r[3]) : "r"(addr));
}

// ---------------------------------------------------------------------------
// fused 3-plane split-bf16 GEMM: C = Ah*Bh^T + Ah*Bl^T + Al*Bh^T
// block tile 128x128, 8 warps (4M x 2N), warp tile 32x64, K chunk 32,
// cp.async double-buffered, ldmatrix, ONE sync per iter, spacing-4 MMAs,
// panel-swizzled 1D grid (GXP bx-tiles x all by per panel).
// ---------------------------------------------------------------------------
#define RS 40
#define TILE_H (128 * RS)
#define GEMM_SMEM (2 * 4 * TILE_H * 2)   // 81920 bytes
#define GXP 8

__global__ void __launch_bounds__(256, 2) mma_gemm_kernel(
    const __nv_bfloat16* __restrict__ Ah, const __nv_bfloat16* __restrict__ Al,
    const __nv_bfloat16* __restrict__ Bh, const __nv_bfloat16* __restrict__ Bl,
    float* __restrict__ C, int Kd, int N)
{
    extern __shared__ __align__(16) __nv_bfloat16 sm[];
    const int t = threadIdx.x, lane = t & 31, w = t >> 5;
    const int wm = (w & 3) * 32, wn = (w >> 2) * 64;
    const int grp = lane >> 2, q = lane & 3;

    const int panel_sz = GXP * (Mtot / 128);
    const int panel = blockIdx.x / panel_sz;
    const int rem   = blockIdx.x % panel_sz;
    const int bx = panel * GXP + (rem % GXP);
    const int by = rem / GXP;

    const int kiters = Kd >> 5;

    float acc[2][8][4];
#pragma unroll
    for (int mi = 0; mi < 2; mi++)
#pragma unroll
        for (int ni = 0; ni < 8; ni++)
#pragma unroll
            for (int j = 0; j < 4; j++) acc[mi][ni][j] = 0.f;

    const int c0 = t, c1 = t + 256;
    const int r0 = c0 >> 2, s0 = c0 & 3;
    const int r1 = c1 >> 2, s1 = c1 & 3;

    uint32_t smb = smem_u32(sm);

    auto issue = [&](int stage, int kc) {
        size_t k0 = (size_t)kc << 5;
        const __nv_bfloat16* srcs[4] = {
            Ah + (size_t)(by * 128) * Kd, Al + (size_t)(by * 128) * Kd,
            Bh + (size_t)(bx * 128) * Kd, Bl + (size_t)(bx * 128) * Kd };
#pragma unroll
        for (int ti = 0; ti < 4; ti++) {
            uint32_t base = smb + (uint32_t)((stage * 4 + ti) * TILE_H) * 2;
            cp_async16(base + (r0 * RS + s0 * 8) * 2,
                       srcs[ti] + (size_t)r0 * Kd + k0 + s0 * 8);
            cp_async16(base + (r1 * RS + s1 * 8) * 2,
                       srcs[ti] + (size_t)r1 * Kd + k0 + s1 * 8);
        }
        cp_commit();
    };

    issue(0, 0);

    const int r8  = lane & 7;
    const int hm  = (lane >> 3) & 1;
    const int hk2 = (lane >> 4) & 1;

    for (int it = 0; it < kiters; it++) {
        int buf = it & 1;
        cp_wait<0>();
        __syncthreads();
        if (it + 1 < kiters) issue(buf ^ 1, it + 1);

        uint32_t sahb = smb + (uint32_t)((buf * 4 + 0) * TILE_H) * 2;
        uint32_t salb = smb + (uint32_t)((buf * 4 + 1) * TILE_H) * 2;
        uint32_t sbhb = smb + (uint32_t)((buf * 4 + 2) * TILE_H) * 2;
        uint32_t sblb = smb + (uint32_t)((buf * 4 + 3) * TILE_H) * 2;

#pragma unroll
        for (int ks = 0; ks < 2; ks++) {
            const int k16 = ks * 16;
            uint32_t ah[2][4], al[2][4];
            uint32_t aoff0 = (uint32_t)((wm + hm * 8 + r8) * RS + k16 + hk2 * 8) * 2;
            uint32_t aoff1 = aoff0 + 16 * RS * 2;
            ldsm4(ah[0], sahb + aoff0);
            ldsm4(ah[1], sahb + aoff1);
            ldsm4(al[0], salb + aoff0);
            ldsm4(al[1], salb + aoff1);
#pragma unroll
            for (int pi = 0; pi < 4; pi++) {
                uint32_t boff = (uint32_t)((wn + pi * 16 + hk2 * 8 + r8) * RS + k16 + hm * 8) * 2;
                uint32_t bh4[4], bl4[4];
                ldsm4(bh4, sbhb + boff);
                ldsm4(bl4, sblb + boff);
                int n0 = pi * 2, n1 = pi * 2 + 1;
                mma16816(acc[0][n0], ah[0], bh4 + 0);
                mma16816(acc[1][n0], ah[1], bh4 + 0);
                mma16816(acc[0][n1], ah[0], bh4 + 2);
                mma16816(acc[1][n1], ah[1], bh4 + 2);
                mma16816(acc[0][n0], ah[0], bl4 + 0);
                mma16816(acc[1][n0], ah[1], bl4 + 0);
                mma16816(acc[0][n1], ah[0], bl4 + 2);
                mma16816(acc[1][n1], ah[1], bl4 + 2);
                mma16816(acc[0][n0], al[0], bh4 + 0);
                mma16816(acc[1][n0], al[1], bh4 + 0);
                mma16816(acc[0][n1], al[0], bh4 + 2);
                mma16816(acc[1][n1], al[1], bh4 + 2);
            }
        }
    }

    __syncthreads();
#pragma unroll
    for (int mi = 0; mi < 2; mi++) {
        int row = by * 128 + wm + mi * 16 + grp;
#pragma unroll
        for (int ni = 0; ni < 8; ni++) {
            int col = bx * 128 + wn + ni * 8 + q * 2;
            float2 v0 = make_float2(acc[mi][ni][0], acc[mi][ni][1]);
            float2 v1 = make_float2(acc[mi][ni][2], acc[mi][ni][3]);
            *reinterpret_cast<float2*>(C + (size_t)row * N + col) = v0;
            *reinterpret_cast<float2*>(C + (size_t)(row + 8) * N + col) = v1;
        }
    }
}

// ---------------------------------------------------------------------------
__global__ void split_kernel(const float* __restrict__ src,
                             __nv_bfloat16* __restrict__ hi,
                             __nv_bfloat16* __restrict__ lo)
{
    size_t i = (size_t)blockIdx.x * 256 + threadIdx.x;
    float v = src[i];
    __nv_bfloat16 h = __float2bfloat16(v);
    hi[i] = h;
    lo[i] = __float2bfloat16(v - __bfloat162float(h));
}

__global__ void transpose_split_kernel(const float* __restrict__ W,
                                       __nv_bfloat16* __restrict__ Th,
                                       __nv_bfloat16* __restrict__ Tl,
                                       int K, int N)
{
    __shared__ float tile[32][33];
    int n0 = blockIdx.x * 32, k0 = blockIdx.y * 32;
    int tx = threadIdx.x, ty = threadIdx.y;
#pragma unroll
    for (int j = 0; j < 4; j++)
        tile[ty + j * 8][tx] = W[(size_t)(k0 + ty + j * 8) * N + n0 + tx];
    __syncthreads();
#pragma unroll
    for (int j = 0; j < 4; j++) {
        float v = tile[tx][ty + j * 8];
        __nv_bfloat16 h = __float2bfloat16(v);
        size_t o = (size_t)(n0 + ty + j * 8) * K + k0 + tx;
        Th[o] = h;
        Tl[o] = __float2bfloat16(v - __bfloat162float(h));
    }
}

// ---------------------------------------------------------------------------
__global__ void __launch_bounds__(256) ba_part_kernel(
    const float* __restrict__ x, const float* __restrict__ w_ba)
{
    int ks = blockIdx.x, by = blockIdx.y;
    __shared__ float As[8][128];
    __shared__ float Bs[8][64];
    int t = threadIdx.x, tx = t & 15, ty = t >> 4;
    float acc[8][4];
#pragma unroll
    for (int i = 0; i < 8; i++)
#pragma unroll
        for (int j = 0; j < 4; j++) acc[i][j] = 0.f;

    int arow = t >> 1, acol4 = (t & 1) * 4;
    int brow = t >> 5, bcol2 = (t & 31) * 2;
    const float* Aptr = x + (size_t)(by * 128 + arow) * Hc + ks * 256;

    for (int k0 = 0; k0 < 256; k0 += 8) {
        float4 a4 = *reinterpret_cast<const float4*>(Aptr + k0 + acol4);
        As[acol4 + 0][arow] = a4.x; As[acol4 + 1][arow] = a4.y;
        As[acol4 + 2][arow] = a4.z; As[acol4 + 3][arow] = a4.w;
        float2 b2 = *reinterpret_cast<const float2*>(
            w_ba + (size_t)(ks * 256 + k0 + brow) * 64 + bcol2);
        Bs[brow][bcol2] = b2.x; Bs[brow][bcol2 + 1] = b2.y;
        __syncthreads();
#pragma unroll
        for (int kk = 0; kk < 8; kk++) {
            float a[8], b[4];
#pragma unroll
            for (int i = 0; i < 8; i++) a[i] = As[kk][ty * 8 + i];
#pragma unroll
            for (int j = 0; j < 4; j++) b[j] = Bs[kk][tx * 4 + j];
#pragma unroll
            for (int i = 0; i < 8; i++)
#pragma unroll
                for (int j = 0; j < 4; j++)
                    acc[i][j] = fmaf(a[i], b[j], acc[i][j]);
        }
        __syncthreads();
    }
    float* dst = g_bapart + (size_t)ks * Mtot * 64;
#pragma unroll
    for (int i = 0; i < 8; i++) {
        int row = by * 128 + ty * 8 + i;
        float4 v = make_float4(acc[i][0], acc[i][1], acc[i][2], acc[i][3]);
        *reinterpret_cast<float4*>(dst + (size_t)row * 64 + tx * 4) = v;
    }
}

__global__ void ba_reduce_kernel()
{
    int i = blockIdx.x * 256 + threadIdx.x;
    float s = 0.f;
#pragma unroll
    for (int ks = 0; ks < 8; ks++) s += g_bapart[(size_t)ks * Mtot * 64 + i];
    g_ba[i] = s;
}

// ---------------------------------------------------------------------------
__global__ void conv_qknorm_kernel(const float* __restrict__ conv_w,
                                   const float* __restrict__ conv_b)
{
    int tid = threadIdx.x;
    int c = blockIdx.x * 256 + tid;
    int m = blockIdx.y;
    int s = m & (Sc - 1);
    int col;
    if (c < 2048)      col = (c >> 7) * 768 + (c & 127);
    else if (c < 4096) { int c2 = c - 2048; col = (c2 >> 7) * 768 + 128 + (c2 & 127); }
    else               { int c3 = c - 4096; col = (c3 >> 8) * 768 + 256 + (c3 & 255); }
    float acc = conv_b[c];
    const float* w = conv_w + c * 4;
#pragma unroll
    for (int j = 0; j < 4; j++) {
        int sp = s - 3 + j;
        if (sp >= 0)
            acc = fmaf(g_qkvz[(size_t)(m - 3 + j) * FQ + col], w[j], acc);
    }
    float val = acc / (1.f + expf(-acc));

    if (c < 4096) {
        float ss = val * val;
#pragma unroll
        for (int o = 16; o > 0; o >>= 1) ss += __shfl_xor_sync(0xffffffffu, ss, o);
        __shared__ float rb[8];
        if ((tid & 31) == 0) rb[tid >> 5] = ss;
        __syncthreads();
        int hw = (tid >> 7) * 4;
        float sum = rb[hw] + rb[hw + 1] + rb[hw + 2] + rb[hw + 3];
        if (c < 2048) {
            float rq = rsqrtf(sum + EPSc) * 0.08838834764831845f;
            g_qn[m * 2048 + c] = val * rq;
        } else {
            float rk = rsqrtf(sum + EPSc);
            g_kn[m * 2048 + (c - 2048)] = val * rk;
        }
    } else {
        g_conv[(size_t)m * CDc + c] = val;
    }
}

__global__ void gbeta_kernel(const float* __restrict__ a_log,
                             const float* __restrict__ dt_bias)
{
    int idx = blockIdx.x * 256 + threadIdx.x;
    int m = idx >> 5, hv = idx & 31;
    int hk = hv >> 1, gi = hv & 1;
    float bval = g_ba[m * 64 + hk * 4 + gi];
    float aval = g_ba[m * 64 + hk * 4 + 2 + gi];
    float x = aval + dt_bias[hv];
    float sp = (x > 20.f) ? x : log1pf(expf(x));
    g_gg[idx]   = -expf(a_log[hv]) * sp;
    g_beta[idx] = 1.f / (1.f + expf(-bval));
}

// ---------------------------------------------------------------------------
// gated delta scan, scaled state: S_true = c * S^, c *= exp(g) per step.
// loop1: P = k.S^; delta = (v - c*P)*beta; dc = delta/c;
// loop2: S^ += k*dc; o = c*(q.S^). Renorm when c < 1e-6.
// depth-2 prefetch, 128 blocks = (b,hv,vhalf), 256 threads.
// ---------------------------------------------------------------------------
__global__ void __launch_bounds__(256) scan_kernel()
{
    int bid = blockIdx.x;
    int bb = bid >> 6;
    int r = bid & 63;
    int hv = r >> 1, half = r & 1, hk = hv >> 1;
    int t = threadIdx.x;
    int vl = t & 63, qt = t >> 6, dbase = qt * 32;

    float S[32];
#pragma unroll
    for (int i = 0; i < 32; i++) S[i] = 0.f;
    float c = 1.f;

    __shared__ __align__(16) float kq[3][256];
    __shared__ __align__(16) float vsb[3][64];
    __shared__ float gbb[3][2];
    __shared__ float red[4][64], ored[4][64];

    const uint32_t skq = smem_u32(kq);
    const uint32_t svs = smem_u32(vsb);
    const uint32_t sgb = smem_u32(gbb);

    const float* kbase = g_kn + hk * 128;
    const float* qbase = g_qn + hk * 128;
    const float* vbase = g_conv + 4096 + hv * 128 + half * 64;
    const float* gbase = g_gg + hv;
    const float* bbase = g_beta + hv;

    auto prefetch = [&](int buf, int s) {
        int m = bb * Sc + s;
        if (t < 32)
            cp_async16(skq + buf * 1024 + t * 16, kbase + (size_t)m * 2048 + t * 4);
        else if (t < 64)
            cp_async16(skq + buf * 1024 + 512 + (t - 32) * 16,
                       qbase + (size_t)m * 2048 + (t - 32) * 4);
        else if (t < 80)
            cp_async16(svs + buf * 256 + (t - 64) * 16,
                       vbase + (size_t)m * CDc + (t - 64) * 4);
        else if (t == 80)
            cp_async4(sgb + buf * 8, gbase + m * 32);
        else if (t == 81)
            cp_async4(sgb + buf * 8 + 4, bbase + m * 32);
    };

    prefetch(0, 0); cp_commit();
    prefetch(1, 1); cp_commit();

    size_t obase = (size_t)bb * Sc * 4096 + hv * 128 + half * 64;

    for (int s = 0; s < Sc; s++) {
        int buf = s % 3;
        cp_wait<1>();
        __syncthreads();                      // bar1
        if (s + 2 < Sc) { prefetch((s + 2) % 3, s + 2); cp_commit(); }

        if (s > 0 && t < 64)
            g_opre[obase + (size_t)(s - 1) * 4096 + t] =
                ored[0][t] + ored[1][t] + ored[2][t] + ored[3][t];

        float eg   = expf(gbb[buf][0]);
        float beta = gbb[buf][1];
        const float* ks = kq[buf];
        const float* qs = kq[buf] + 128;
        const float* vs = vsb[buf];
        c *= eg;

        float p0 = 0.f, p1 = 0.f, p2 = 0.f, p3 = 0.f;
#pragma unroll
        for (int d = 0; d < 32; d += 4) {
            p0 = fmaf(ks[dbase + d],     S[d],     p0);
            p1 = fmaf(ks[dbase + d + 1], S[d + 1], p1);
            p2 = fmaf(ks[dbase + d + 2], S[d + 2], p2);
            p3 = fmaf(ks[dbase + d + 3], S[d + 3], p3);
        }
        red[qt][vl] = (p0 + p1) + (p2 + p3);
        __syncthreads();                      // bar2

        float P = red[0][vl] + red[1][vl] + red[2][vl] + red[3][vl];
        float delta = (vs[vl] - c * P) * beta;
        float dc = __fdividef(delta, c);
        float o0 = 0.f, o1 = 0.f, o2 = 0.f, o3 = 0.f;
#pragma unroll
        for (int d = 0; d < 32; d += 4) {
            S[d]     = fmaf(ks[dbase + d],     dc, S[d]);
            S[d + 1] = fmaf(ks[dbase + d + 1], dc, S[d + 1]);
            S[d + 2] = fmaf(ks[dbase + d + 2], dc, S[d + 2]);
            S[d + 3] = fmaf(ks[dbase + d + 3], dc, S[d + 3]);
            o0 = fmaf(qs[dbase + d],     S[d],     o0);
            o1 = fmaf(qs[dbase + d + 1], S[d + 1], o1);
            o2 = fmaf(qs[dbase + d + 2], S[d + 2], o2);
            o3 = fmaf(qs[dbase + d + 3], S[d + 3], o3);
        }
        ored[qt][vl] = ((o0 + o1) + (o2 + o3)) * c;

        if (c < 1e-6f) {                      // uniform across block
#pragma unroll
            for (int d = 0; d < 32; d++) S[d] *= c;
            c = 1.f;
        }
    }
    __syncthreads();
    if (t < 64)
        g_opre[obase + (size_t)(Sc - 1) * 4096 + t] =
            ored[0][t] + ored[1][t] + ored[2][t] + ored[3][t];
}

// ---------------------------------------------------------------------------
__global__ void gate_norm_kernel(const float* __restrict__ norm_w)
{
    int m = blockIdx.x, hv = blockIdx.y, d = threadIdx.x;
    int hk = hv >> 1, gi = hv & 1;
    float z = g_qkvz[(size_t)m * FQ + hk * 768 + 512 + gi * 128 + d];
    float o = g_opre[(size_t)m * 4096 + hv * 128 + d] * (z / (1.f + expf(-z)));
    float ss = o * o;
#pragma unroll
    for (int off = 16; off > 0; off >>= 1) ss += __shfl_xor_sync(0xffffffffu, ss, off);
    __shared__ float rb[4];
    if ((d & 31) == 0) rb[d >> 5] = ss;
    __syncthreads();
    float sum = rb[0] + rb[1] + rb[2] + rb[3];
    float rs = rsqrtf(sum * (1.f / 128.f) + EPSc);
    float v = o * rs * norm_w[d];
    __nv_bfloat16 h = __float2bfloat16(v);
    size_t idx = (size_t)m * 4096 + hv * 128 + d;
    g_ohi[idx] = h;
    g_olo[idx] = __float2bfloat16(v - __bfloat162float(h));
}

// ---------------------------------------------------------------------------
extern "C" void kernel_launch(void* const* d_in, const int* in_sizes, int n_in,
                              void* d_out, int out_size)
{
    const float* x       = (const float*)d_in[0];
    const float* w_qkvz  = (const float*)d_in[1];
    const float* w_ba    = (const float*)d_in[2];
    const float* a_log   = (const float*)d_in[3];
    const float* dt_bias = (const float*)d_in[4];
    const float* conv_w  = (const float*)d_in[5];
    const float* conv_b  = (const float*)d_in[6];
    const float* norm_w  = (const float*)d_in[7];
    const float* w_o     = (const float*)d_in[8];
    float* out = (float*)d_out;

    float *p_qkvz;
    __nv_bfloat16 *p_xhi, *p_xlo, *p_bqhi, *p_bqlo, *p_bohi, *p_bolo, *p_ohi, *p_olo;
    cudaGetSymbolAddress((void**)&p_qkvz, g_qkvz);
    cudaGetSymbolAddress((void**)&p_xhi,  g_xhi);
    cudaGetSymbolAddress((void**)&p_xlo,  g_xlo);
    cudaGetSymbolAddress((void**)&p_bqhi, g_bqhi);
    cudaGetSymbolAddress((void**)&p_bqlo, g_bqlo);
    cudaGetSymbolAddress((void**)&p_bohi, g_bohi);
    cudaGetSymbolAddress((void**)&p_bolo, g_bolo);
    cudaGetSymbolAddress((void**)&p_ohi,  g_ohi);
    cudaGetSymbolAddress((void**)&p_olo,  g_olo);

    cudaFuncSetAttribute(mma_gemm_kernel,
                         cudaFuncAttributeMaxDynamicSharedMemorySize, GEMM_SMEM);

    split_kernel<<<(Mtot * Hc) / 256, 256>>>(x, p_xhi, p_xlo);
    transpose_split_kernel<<<dim3(FQ / 32, Hc / 32), dim3(32, 8)>>>(w_qkvz, p_bqhi, p_bqlo, Hc, FQ);
    transpose_split_kernel<<<dim3(Hc / 32, 4096 / 32), dim3(32, 8)>>>(w_o, p_bohi, p_bolo, 4096, Hc);

    // K1: qkvz = x @ w_qkvz  (128x128 tiles, 1D swizzled grid)
    mma_gemm_kernel<<<(FQ / 128) * (Mtot / 128), 256, GEMM_SMEM>>>(
        p_xhi, p_xlo, p_bqhi, p_bqlo, p_qkvz, Hc, FQ);
    // K2: ba = x @ w_ba (split-K x8 + reduce)
    ba_part_kernel<<<dim3(8, Mtot / 128), 256>>>(x, w_ba);
    ba_reduce_kernel<<<(Mtot * 64) / 256, 256>>>();
    // K3+K4: conv + silu + q/k l2norm
    conv_qknorm_kernel<<<dim3(CDc / 256, Mtot), 256>>>(conv_w, conv_b);
    // K5: gates
    gbeta_kernel<<<(Mtot * HVc) / 256, 256>>>(a_log, dt_bias);
    // K6: recurrent scan (scaled-state)
    scan_kernel<<<128, 256>>>();
    // K7: gate + rmsnorm + bf16 split
    gate_norm_kernel<<<dim3(Mtot, HVc), 128>>>(norm_w);
    // K8: out = o @ w_o
    mma_gemm_kernel<<<(Hc / 128) * (Mtot / 128), 256, GEMM_SMEM>>>(
        p_ohi, p_olo, p_bohi, p_bolo, out, 4096, Hc);
}